// round 15
// baseline (speedup 1.0000x reference)
#include <cuda_runtime.h>

#define NN  100000
#define EE  3200000
#define FIN 128
#define H1  16
#define H2  8
#define NEG 0.2f
#define CAP 128        // padded per-node slot capacity (mean deg 32; overflow-safe)
#define NB_L1 12500    // blocks for the l1-GEMM role (8 warps x 12500 = 100K nodes)
#define NB_BUILD ((EE + 255) / 256)

// ---------------- scratch (device globals) -----------------------------------
__device__ int    g_deg[NN];          // zero at load; re-zeroed by agg2 tail each run
__device__ int    g_slot[NN * CAP];   // src ids
__device__ float4 g_h1e[NN * 8];      // [16 feats | e1s | pad] 128B records
__device__ float  g_e1d[NN];
__device__ float4 g_h2e[NN * 4];      // [8 feats | e2s | pad] 64B records
__device__ float  g_e2d[NN];
__device__ int    g_is64;

__device__ __forceinline__ float lrelu(float e) { return e > 0.f ? e : NEG * e; }

// ---------------- int64 vs int32 layout sniff (1 block) ----------------------
__global__ void k_sniff(const int* __restrict__ ei) {
    int lane = threadIdx.x;
    int any = 0;
    #pragma unroll
    for (int k = 0; k < 4; k++) any |= ei[2 * (lane * 4 + k) + 1];
    unsigned b = __ballot_sync(0xffffffffu, any != 0);
    if (lane == 0) g_is64 = (b == 0u) ? 1 : 0;
}

// ---------------- fused: l1 GEMM (blocks < NB_L1) + bucket build (rest) ------
__global__ void k_build_l1(const int* __restrict__ ei,
                           const float* __restrict__ x,
                           const float* __restrict__ W1,
                           const float* __restrict__ a1s,
                           const float* __restrict__ a1d) {
    int tid = threadIdx.x;
    if (blockIdx.x >= NB_L1) {
        // ---- build role: 2 scattered ops per edge ----
        int e = (blockIdx.x - NB_L1) * blockDim.x + tid;
        if (e >= EE) return;
        int s, d;
        if (g_is64) { int4 v = __ldg((const int4*)ei + e); s = v.x; d = v.z; }
        else        { int2 v = __ldg((const int2*)ei + e); s = v.x; d = v.y; }
        int pos = atomicAdd(&g_deg[d], 1);
        if (pos < CAP) g_slot[d * CAP + pos] = s;
        return;
    }
    // ---- l1 GEMM role: warp per node ----
    __shared__ float Wt[H1 * FIN];
    __shared__ float as[H1], ad[H1];
    for (int i = tid; i < H1 * FIN; i += blockDim.x) {
        int j = i / FIN, k = i - j * FIN;
        Wt[i] = W1[k * H1 + j];
    }
    if (tid < H1) { as[tid] = a1s[tid]; ad[tid] = a1d[tid]; }
    __syncthreads();

    int warp = tid >> 5, lane = tid & 31;
    int node = blockIdx.x * 8 + warp;
    if (node >= NN) return;

    float4 xv = ((const float4*)x)[node * 32 + lane];
    float acc[H1];
    #pragma unroll
    for (int j = 0; j < H1; j++) {
        float4 w = ((const float4*)Wt)[j * 32 + lane];
        acc[j] = xv.x * w.x + xv.y * w.y + xv.z * w.z + xv.w * w.w;
    }
    #pragma unroll
    for (int j = 0; j < H1; j++) {
        #pragma unroll
        for (int off = 16; off; off >>= 1)
            acc[j] += __shfl_xor_sync(0xffffffffu, acc[j], off);
    }
    if (lane == 0) {
        float es = 0.f, ed = 0.f;
        #pragma unroll
        for (int j = 0; j < H1; j++) { es += acc[j] * as[j]; ed += acc[j] * ad[j]; }
        g_e1d[node] = ed;
        float4* hp = g_h1e + node * 8;
        hp[0] = make_float4(acc[0],  acc[1],  acc[2],  acc[3]);
        hp[1] = make_float4(acc[4],  acc[5],  acc[6],  acc[7]);
        hp[2] = make_float4(acc[8],  acc[9],  acc[10], acc[11]);
        hp[3] = make_float4(acc[12], acc[13], acc[14], acc[15]);
        hp[4] = make_float4(es, 0.f, 0.f, 0.f);
    }
}

// ---------------- agg1: 8-lane groups, 1 record wavefront per edge -----------
__global__ void k_agg1(const float* __restrict__ W2,
                       const float* __restrict__ a2s,
                       const float* __restrict__ a2d,
                       const float* __restrict__ b1) {
    __shared__ float Ws[H1 * H2];
    __shared__ float as[H2], ad[H2];
    __shared__ float4 bs4[4];
    int tid = threadIdx.x;
    if (tid < H1 * H2) Ws[tid] = W2[tid];
    if (tid < H2) { as[tid] = a2s[tid]; ad[tid] = a2d[tid]; }
    if (tid < 4)  bs4[tid] = ((const float4*)b1)[tid];
    __syncthreads();

    int warp = tid >> 5, lane = tid & 31;
    int node = blockIdx.x * 8 + warp;
    if (node >= NN) return;

    int row = node * CAP;
    int deg = __ldg(&g_deg[node]);
    deg = deg < CAP ? deg : CAP;
    float ed1 = __ldg(&g_e1d[node]);

    int g = lane >> 3, fl = lane & 7;   // 4 groups of 8; 4 edges per warp-iter
    int gbase = lane & 24;              // first lane of this group
    unsigned gmask = 0xFFu << gbase;    // this group's lanes (converged together)
    float4 acc = make_float4(0.f, 0.f, 0.f, 0.f);
    float wsum = 0.f;

    // self loop: group 0 only (lanes 0-7 converged; mask covers exactly them)
    if (g == 0) {
        float4 v = __ldg(g_h1e + node * 8 + fl);
        float es = __shfl_sync(0xFFu, v.x, 4);         // lane 4 chunk .x = e1s
        float w = __expf(lrelu(es + ed1));
        if (fl >= 4) v = make_float4(0.f, 0.f, 0.f, 0.f);
        acc = make_float4(w * v.x, w * v.y, w * v.z, w * v.w);
        if (fl == 0) wsum = w;
    }
    #pragma unroll 4
    for (int idx = g; idx < deg; idx += 4) {
        int s = __ldg(&g_slot[row + idx]);             // group lanes share addr
        float4 v = __ldg(g_h1e + s * 8 + fl);          // 1 line per edge
        float es = __shfl_sync(gmask, v.x, gbase + 4); // group-masked broadcast
        float w = __expf(lrelu(es + ed1));
        if (fl >= 4) v = make_float4(0.f, 0.f, 0.f, 0.f);
        acc.x = fmaf(w, v.x, acc.x); acc.y = fmaf(w, v.y, acc.y);
        acc.z = fmaf(w, v.z, acc.z); acc.w = fmaf(w, v.w, acc.w);
        if (fl == 0) wsum += w;
    }
    #pragma unroll
    for (int off = 8; off < 32; off <<= 1) {
        acc.x += __shfl_xor_sync(0xffffffffu, acc.x, off);
        acc.y += __shfl_xor_sync(0xffffffffu, acc.y, off);
        acc.z += __shfl_xor_sync(0xffffffffu, acc.z, off);
        acc.w += __shfl_xor_sync(0xffffffffu, acc.w, off);
        wsum  += __shfl_xor_sync(0xffffffffu, wsum, off);
    }
    // wsum lives on lanes {0,8,16,24}; spread to all lanes
    wsum += __shfl_xor_sync(0xffffffffu, wsum, 4);
    wsum += __shfl_xor_sync(0xffffffffu, wsum, 2);
    wsum += __shfl_xor_sync(0xffffffffu, wsum, 1);
    // lanes 0-3 hold feature totals [fl*4 .. fl*4+3]; lanes 4-7 zeros

    float inv = 1.f / wsum;
    int fl4 = lane & 3;
    float4 bb = bs4[fl4];
    float4 o;
    o.x = fmaf(acc.x, inv, bb.x); o.x = o.x > 0.f ? o.x : 0.f;
    o.y = fmaf(acc.y, inv, bb.y); o.y = o.y > 0.f ? o.y : 0.f;
    o.z = fmaf(acc.z, inv, bb.z); o.z = o.z > 0.f ? o.z : 0.f;
    o.w = fmaf(acc.w, inv, bb.w); o.w = o.w > 0.f ? o.w : 0.f;

    // reconstruct 16 o values (sourced from lanes 0-3), 16->8 transform
    int j = lane & 7;
    float h2v = 0.f;
    #pragma unroll
    for (int k = 0; k < H1; k++) {
        int srcl = k >> 2;
        float comp = (k & 3) == 0 ? o.x : (k & 3) == 1 ? o.y : (k & 3) == 2 ? o.z : o.w;
        float ok = __shfl_sync(0xffffffffu, comp, srcl);
        h2v = fmaf(ok, Ws[k * H2 + j], h2v);
    }
    float pes = h2v * as[j];
    float ped = h2v * ad[j];
    #pragma unroll
    for (int off = 1; off < 8; off <<= 1) {
        pes += __shfl_xor_sync(0xffffffffu, pes, off);
        ped += __shfl_xor_sync(0xffffffffu, ped, off);
    }
    if (lane == 0) g_e2d[node] = ped;
    // pack h2 record: lanes 0,1 assemble two float4s via shfl, lane 2 writes e2s
    float c0 = __shfl_sync(0xffffffffu, h2v, (lane & 1) * 4 + 0);
    float c1 = __shfl_sync(0xffffffffu, h2v, (lane & 1) * 4 + 1);
    float c2 = __shfl_sync(0xffffffffu, h2v, (lane & 1) * 4 + 2);
    float c3 = __shfl_sync(0xffffffffu, h2v, (lane & 1) * 4 + 3);
    if (lane < 2)       g_h2e[node * 4 + lane] = make_float4(c0, c1, c2, c3);
    else if (lane == 2) g_h2e[node * 4 + 2] = make_float4(pes, 0.f, 0.f, 0.f);
}

// ---------------- agg2: 4-lane groups, 1 record wavefront per edge -----------
__global__ void k_agg2(const float* __restrict__ Wf,
                       const float* __restrict__ bf,
                       const float* __restrict__ b2,
                       float* __restrict__ out) {
    __shared__ float4 wf4[2], bs4[2];
    __shared__ float bfv;
    int tid = threadIdx.x;
    if (tid < 2) { wf4[tid] = ((const float4*)Wf)[tid]; bs4[tid] = ((const float4*)b2)[tid]; }
    if (tid == 0) bfv = bf[0];
    __syncthreads();

    int warp = tid >> 5, lane = tid & 31;
    int node = blockIdx.x * 8 + warp;
    if (node >= NN) return;

    int row = node * CAP;
    int deg = __ldg(&g_deg[node]);
    deg = deg < CAP ? deg : CAP;
    float ed2 = __ldg(&g_e2d[node]);

    int g = lane >> 2, fl = lane & 3;   // 8 groups of 4; 8 edges per warp-iter
    int gbase = lane & 28;
    unsigned gmask = 0xFu << gbase;
    float4 acc = make_float4(0.f, 0.f, 0.f, 0.f);
    float wsum = 0.f;

    if (g == 0) {                       // self loop (lanes 0-3 converged)
        float4 v = __ldg(g_h2e + node * 4 + fl);
        float es = __shfl_sync(0xFu, v.x, 2);          // lane 2 chunk .x = e2s
        float w = __expf(lrelu(es + ed2));
        if (fl >= 2) v = make_float4(0.f, 0.f, 0.f, 0.f);
        acc = make_float4(w * v.x, w * v.y, w * v.z, w * v.w);
        if (fl == 0) wsum = w;
    }
    #pragma unroll 4
    for (int idx = g; idx < deg; idx += 8) {
        int s = __ldg(&g_slot[row + idx]);             // group lanes share addr
        float4 v = __ldg(g_h2e + s * 4 + fl);
        float es = __shfl_sync(gmask, v.x, gbase + 2); // group-masked broadcast
        float w = __expf(lrelu(es + ed2));
        if (fl >= 2) v = make_float4(0.f, 0.f, 0.f, 0.f);
        acc.x = fmaf(w, v.x, acc.x); acc.y = fmaf(w, v.y, acc.y);
        acc.z = fmaf(w, v.z, acc.z); acc.w = fmaf(w, v.w, acc.w);
        if (fl == 0) wsum += w;
    }
    #pragma unroll
    for (int off = 4; off < 32; off <<= 1) {
        acc.x += __shfl_xor_sync(0xffffffffu, acc.x, off);
        acc.y += __shfl_xor_sync(0xffffffffu, acc.y, off);
        acc.z += __shfl_xor_sync(0xffffffffu, acc.z, off);
        acc.w += __shfl_xor_sync(0xffffffffu, acc.w, off);
        wsum  += __shfl_xor_sync(0xffffffffu, wsum, off);
    }
    wsum += __shfl_xor_sync(0xffffffffu, wsum, 2);
    wsum += __shfl_xor_sync(0xffffffffu, wsum, 1);
    // lane0: feats 0-3, lane1: feats 4-7 (fully reduced)

    float inv = 1.f / wsum;
    float p = 0.f;
    if ((lane & 3) < 2) {
        int fl4 = lane & 1;
        float4 bb = bs4[fl4], ww = wf4[fl4];
        float tx;
        tx = fmaf(acc.x, inv, bb.x); tx = tx > 0.f ? tx : 0.f; p = fmaf(tx, ww.x, p);
        tx = fmaf(acc.y, inv, bb.y); tx = tx > 0.f ? tx : 0.f; p = fmaf(tx, ww.y, p);
        tx = fmaf(acc.z, inv, bb.z); tx = tx > 0.f ? tx : 0.f; p = fmaf(tx, ww.z, p);
        tx = fmaf(acc.w, inv, bb.w); tx = tx > 0.f ? tx : 0.f; p = fmaf(tx, ww.w, p);
    }
    p += __shfl_xor_sync(0xffffffffu, p, 1);
    if (lane == 0) {
        out[node] = p + bfv;
        g_deg[node] = 0;                // restore invariant for next run
    }
}

// ---------------- launch ------------------------------------------------------
extern "C" void kernel_launch(void* const* d_in, const int* in_sizes, int n_in,
                              void* d_out, int out_size) {
    const float* x   = (const float*)d_in[0];
    const int*   ei  = (const int*)d_in[1];
    const float* W1  = (const float*)d_in[2];
    const float* a1s = (const float*)d_in[3];
    const float* a1d = (const float*)d_in[4];
    const float* b1  = (const float*)d_in[5];
    const float* W2  = (const float*)d_in[6];
    const float* a2s = (const float*)d_in[7];
    const float* a2d = (const float*)d_in[8];
    const float* b2  = (const float*)d_in[9];
    const float* Wf  = (const float*)d_in[10];
    const float* bf  = (const float*)d_in[11];
    float* out = (float*)d_out;

    k_sniff<<<1, 32>>>(ei);
    k_build_l1<<<NB_L1 + NB_BUILD, 256>>>(ei, x, W1, a1s, a1d);
    k_agg1<<<(NN + 7) / 8, 256>>>(W2, a2s, a2d, b1);
    k_agg2<<<(NN + 7) / 8, 256>>>(Wf, bf, b2, out);
}

// round 16
// speedup vs baseline: 1.2424x; 1.2424x over previous
#include <cuda_runtime.h>

#define NN  100000
#define EE  3200000
#define FIN 128
#define H1  16
#define H2  8
#define NEG 0.2f
#define CAP 128        // padded per-node slot capacity (mean deg 32; overflow-safe)
#define NB_L1 12500    // GEMM-role blocks (8 warps x 12500 = 100K nodes)
#define NB_BUILD 12500 // build-role blocks (256 thr x 12500 = 3.2M edges)

// ---------------- scratch (device globals) -----------------------------------
__device__ int   g_deg[NN];           // zero at load; re-zeroed by agg2 tail each run
__device__ int   g_slot[NN * CAP];    // src ids
__device__ float g_h1[NN * H1];
__device__ float g_e1s[NN];
__device__ float g_e1d[NN];
__device__ float g_h2[NN * H2];
__device__ float g_e2s[NN];
__device__ float g_e2d[NN];
__device__ int   g_is64;

__device__ __forceinline__ float lrelu(float e) { return e > 0.f ? e : NEG * e; }

// ---------------- int64 vs int32 layout sniff (1 block) ----------------------
__global__ void k_sniff(const int* __restrict__ ei) {
    int lane = threadIdx.x;
    int any = 0;
    #pragma unroll
    for (int k = 0; k < 4; k++) any |= ei[2 * (lane * 4 + k) + 1];
    unsigned b = __ballot_sync(0xffffffffu, any != 0);
    if (lane == 0) g_is64 = (b == 0u) ? 1 : 0;
}

// ---------------- fused: l1 GEMM (even blocks) + bucket build (odd blocks) ---
// Parity interleave => both roles co-resident from wave 1 (true overlap).
__global__ void k_build_l1(const int* __restrict__ ei,
                           const float* __restrict__ x,
                           const float* __restrict__ W1,
                           const float* __restrict__ a1s,
                           const float* __restrict__ a1d) {
    int tid = threadIdx.x;
    if (blockIdx.x & 1) {
        // ---- build role: 2 scattered ops per edge ----
        int e = (blockIdx.x >> 1) * blockDim.x + tid;
        if (e >= EE) return;
        int s, d;
        if (g_is64) { int4 v = __ldg((const int4*)ei + e); s = v.x; d = v.z; }
        else        { int2 v = __ldg((const int2*)ei + e); s = v.x; d = v.y; }
        int pos = atomicAdd(&g_deg[d], 1);
        if (pos < CAP) g_slot[d * CAP + pos] = s;
        return;
    }
    // ---- l1 GEMM role: warp per node ----
    __shared__ float Wt[H1 * FIN];
    __shared__ float as[H1], ad[H1];
    for (int i = tid; i < H1 * FIN; i += blockDim.x) {
        int j = i / FIN, k = i - j * FIN;
        Wt[i] = W1[k * H1 + j];
    }
    if (tid < H1) { as[tid] = a1s[tid]; ad[tid] = a1d[tid]; }
    __syncthreads();

    int warp = tid >> 5, lane = tid & 31;
    int node = (blockIdx.x >> 1) * 8 + warp;
    if (node >= NN) return;

    float4 xv = ((const float4*)x)[node * 32 + lane];
    float acc[H1];
    #pragma unroll
    for (int j = 0; j < H1; j++) {
        float4 w = ((const float4*)Wt)[j * 32 + lane];
        acc[j] = xv.x * w.x + xv.y * w.y + xv.z * w.z + xv.w * w.w;
    }
    #pragma unroll
    for (int j = 0; j < H1; j++) {
        #pragma unroll
        for (int off = 16; off; off >>= 1)
            acc[j] += __shfl_xor_sync(0xffffffffu, acc[j], off);
    }
    if (lane == 0) {
        float es = 0.f, ed = 0.f;
        #pragma unroll
        for (int j = 0; j < H1; j++) { es += acc[j] * as[j]; ed += acc[j] * ad[j]; }
        g_e1s[node] = es;
        g_e1d[node] = ed;
        float4* hp = (float4*)(g_h1 + node * H1);
        hp[0] = make_float4(acc[0],  acc[1],  acc[2],  acc[3]);
        hp[1] = make_float4(acc[4],  acc[5],  acc[6],  acc[7]);
        hp[2] = make_float4(acc[8],  acc[9],  acc[10], acc[11]);
        hp[3] = make_float4(acc[12], acc[13], acc[14], acc[15]);
    }
}

// ---------------- agg1: 4-lane groups, inline redundant expf, no smem --------
__global__ void k_agg1(const float* __restrict__ W2,
                       const float* __restrict__ a2s,
                       const float* __restrict__ a2d,
                       const float* __restrict__ b1) {
    __shared__ float Ws[H1 * H2];
    __shared__ float as[H2], ad[H2];
    __shared__ float4 bs4[4];
    int tid = threadIdx.x;
    if (tid < H1 * H2) Ws[tid] = W2[tid];
    if (tid < H2) { as[tid] = a2s[tid]; ad[tid] = a2d[tid]; }
    if (tid < 4)  bs4[tid] = ((const float4*)b1)[tid];
    __syncthreads();

    int warp = tid >> 5, lane = tid & 31;
    int node = blockIdx.x * 8 + warp;
    if (node >= NN) return;

    int row = node * CAP;
    int deg = __ldg(&g_deg[node]);
    deg = deg < CAP ? deg : CAP;
    float ed1 = __ldg(&g_e1d[node]);

    int g = lane >> 2, fl4 = lane & 3;
    float4 acc = make_float4(0.f, 0.f, 0.f, 0.f);
    float wsum = 0.f;
    if (g == 0) {                                   // self loop (group 0 only)
        float w = __expf(lrelu(__ldg(&g_e1s[node]) + ed1));
        float4 h = __ldg((const float4*)(g_h1 + node * H1) + fl4);
        acc = make_float4(w * h.x, w * h.y, w * h.z, w * h.w);
        wsum = w;
    }
    #pragma unroll 4
    for (int idx = g; idx < deg; idx += 8) {        // 8 edges/iter per warp
        int s   = __ldg(&g_slot[row + idx]);        // group lanes share addr
        float w = __expf(lrelu(__ldg(&g_e1s[s]) + ed1));   // redundant x4, cheap
        float4 h = __ldg((const float4*)(g_h1 + s * H1) + fl4);
        acc.x = fmaf(w, h.x, acc.x); acc.y = fmaf(w, h.y, acc.y);
        acc.z = fmaf(w, h.z, acc.z); acc.w = fmaf(w, h.w, acc.w);
        wsum += w;
    }
    #pragma unroll
    for (int off = 4; off < 32; off <<= 1) {
        acc.x += __shfl_xor_sync(0xffffffffu, acc.x, off);
        acc.y += __shfl_xor_sync(0xffffffffu, acc.y, off);
        acc.z += __shfl_xor_sync(0xffffffffu, acc.z, off);
        acc.w += __shfl_xor_sync(0xffffffffu, acc.w, off);
        wsum  += __shfl_xor_sync(0xffffffffu, wsum, off);
    }
    // every lane now holds totals for features 4*fl4 .. 4*fl4+3
    float inv = 1.f / wsum;
    float4 bb = bs4[fl4];
    float4 o;
    o.x = fmaf(acc.x, inv, bb.x); o.x = o.x > 0.f ? o.x : 0.f;
    o.y = fmaf(acc.y, inv, bb.y); o.y = o.y > 0.f ? o.y : 0.f;
    o.z = fmaf(acc.z, inv, bb.z); o.z = o.z > 0.f ? o.z : 0.f;
    o.w = fmaf(acc.w, inv, bb.w); o.w = o.w > 0.f ? o.w : 0.f;

    // reconstruct all 16 o values (static shfls), 16->8 transform
    int j = lane & 7;
    float h2v = 0.f;
    #pragma unroll
    for (int k = 0; k < H1; k++) {
        int srcl = k >> 2;
        float comp = (k & 3) == 0 ? o.x : (k & 3) == 1 ? o.y : (k & 3) == 2 ? o.z : o.w;
        float ok = __shfl_sync(0xffffffffu, comp, srcl);
        h2v = fmaf(ok, Ws[k * H2 + j], h2v);
    }
    float pes = h2v * as[j];
    float ped = h2v * ad[j];
    #pragma unroll
    for (int off = 1; off < 8; off <<= 1) {
        pes += __shfl_xor_sync(0xffffffffu, pes, off);
        ped += __shfl_xor_sync(0xffffffffu, ped, off);
    }
    if (lane == 0) { g_e2s[node] = pes; g_e2d[node] = ped; }
    if (lane < 8)  g_h2[node * H2 + lane] = h2v;
}

// ---------------- agg2: 2-lane groups, inline expf, projection, deg reset ----
__global__ void k_agg2(const float* __restrict__ Wf,
                       const float* __restrict__ bf,
                       const float* __restrict__ b2,
                       float* __restrict__ out) {
    __shared__ float4 wf4[2], bs4[2];
    __shared__ float bfv;
    int tid = threadIdx.x;
    if (tid < 2) { wf4[tid] = ((const float4*)Wf)[tid]; bs4[tid] = ((const float4*)b2)[tid]; }
    if (tid == 0) bfv = bf[0];
    __syncthreads();

    int warp = tid >> 5, lane = tid & 31;
    int node = blockIdx.x * 8 + warp;
    if (node >= NN) return;

    int row = node * CAP;
    int deg = __ldg(&g_deg[node]);
    deg = deg < CAP ? deg : CAP;
    float ed2 = __ldg(&g_e2d[node]);

    int g = lane >> 1, fl4 = lane & 1;
    float4 acc = make_float4(0.f, 0.f, 0.f, 0.f);
    float wsum = 0.f;
    if (g == 0) {                                   // self loop (lanes 0,1)
        float w = __expf(lrelu(__ldg(&g_e2s[node]) + ed2));
        float4 h = __ldg((const float4*)(g_h2 + node * H2) + fl4);
        acc = make_float4(w * h.x, w * h.y, w * h.z, w * h.w);
        wsum = w;
    }
    #pragma unroll 4
    for (int idx = g; idx < deg; idx += 16) {       // 16 edges/iter per warp
        int s   = __ldg(&g_slot[row + idx]);        // pair lanes share addr
        float w = __expf(lrelu(__ldg(&g_e2s[s]) + ed2));   // redundant x2
        float4 h = __ldg((const float4*)(g_h2 + s * H2) + fl4);
        acc.x = fmaf(w, h.x, acc.x); acc.y = fmaf(w, h.y, acc.y);
        acc.z = fmaf(w, h.z, acc.z); acc.w = fmaf(w, h.w, acc.w);
        wsum += w;
    }
    #pragma unroll
    for (int off = 2; off < 32; off <<= 1) {
        acc.x += __shfl_xor_sync(0xffffffffu, acc.x, off);
        acc.y += __shfl_xor_sync(0xffffffffu, acc.y, off);
        acc.z += __shfl_xor_sync(0xffffffffu, acc.z, off);
        acc.w += __shfl_xor_sync(0xffffffffu, acc.w, off);
        wsum  += __shfl_xor_sync(0xffffffffu, wsum, off);
    }
    float inv = 1.f / wsum;
    float4 bb = bs4[fl4], ww = wf4[fl4];
    float tx, p = 0.f;
    tx = fmaf(acc.x, inv, bb.x); tx = tx > 0.f ? tx : 0.f; p = fmaf(tx, ww.x, p);
    tx = fmaf(acc.y, inv, bb.y); tx = tx > 0.f ? tx : 0.f; p = fmaf(tx, ww.y, p);
    tx = fmaf(acc.z, inv, bb.z); tx = tx > 0.f ? tx : 0.f; p = fmaf(tx, ww.z, p);
    tx = fmaf(acc.w, inv, bb.w); tx = tx > 0.f ? tx : 0.f; p = fmaf(tx, ww.w, p);
    p += __shfl_xor_sync(0xffffffffu, p, 1);
    if (lane == 0) {
        out[node] = p + bfv;
        g_deg[node] = 0;                            // restore invariant for next run
    }
}

// ---------------- launch ------------------------------------------------------
extern "C" void kernel_launch(void* const* d_in, const int* in_sizes, int n_in,
                              void* d_out, int out_size) {
    const float* x   = (const float*)d_in[0];
    const int*   ei  = (const int*)d_in[1];
    const float* W1  = (const float*)d_in[2];
    const float* a1s = (const float*)d_in[3];
    const float* a1d = (const float*)d_in[4];
    const float* b1  = (const float*)d_in[5];
    const float* W2  = (const float*)d_in[6];
    const float* a2s = (const float*)d_in[7];
    const float* a2d = (const float*)d_in[8];
    const float* b2  = (const float*)d_in[9];
    const float* Wf  = (const float*)d_in[10];
    const float* bf  = (const float*)d_in[11];
    float* out = (float*)d_out;

    k_sniff<<<1, 32>>>(ei);
    k_build_l1<<<NB_L1 + NB_BUILD, 256>>>(ei, x, W1, a1s, a1d);
    k_agg1<<<(NN + 7) / 8, 256>>>(W2, a2s, a2d, b1);
    k_agg2<<<(NN + 7) / 8, 256>>>(Wf, bf, b2, out);
}